// round 8
// baseline (speedup 1.0000x reference)
#include <cuda_runtime.h>
#include <cuda_bf16.h>
#include <math.h>

// Problem constants
#define K_ 128
#define J_ 4
#define N_ 64
#define R_ 32
#define T_ 32
#define S_ 256
#define A_ 4
#define D_ 64
#define Z_ (K_*J_)   // 512
#define TM1 (T_-1)   // 31
#define RP1 (R_+1)   // 33

// Output segment offsets (floats)
#define O0 0u
#define O1 4224u
#define O2 8448u
#define O3 12672u
#define O4 16896u
#define O5 287232u
#define O6 291200u
#define O7 295168u
#define O8 549120u
#define O9 4612352u
#define O10 4612480u
#define O11 4612608u

#define LOG10F 2.302585092994045684f
#define LOG4F  1.3862943611198906f

// ---------------- scratch ----------------
__device__ float g_ckept[K_*T_];
__device__ float g_llnew[Z_];
__device__ float g_P1[Z_*16];
__device__ float g_P2[Z_*16];
__device__ int4  g_selinfo[K_];   // {gk, i1, i2, zs}

__device__ __forceinline__ float f_logdf(const float* logdf, int l) {
    int di = 2*l - 3;
    di = max(0, min(2*N_ - 1, di));
    return logdf[di];
}

// ---------------- Kernel 1: kA halves [0,2K) + kB candidates [2K,2K+Z) --------
__global__ void __launch_bounds__(256, 4) k1(
        const int* __restrict__ indexes,
        const int* __restrict__ lc, const float* __restrict__ embt,
        const float* __restrict__ lf, const float* __restrict__ Wstat,
        const int* __restrict__ idx1a, const int* __restrict__ idx2a,
        const float* __restrict__ br1, const float* __restrict__ br2,
        const float* __restrict__ embJ, const float* __restrict__ Wq) {
    int tid = threadIdx.x;
    int warp = tid >> 5, lane = tid & 31;

    if (blockIdx.x < 2*K_) {
        // ----- kA half: rows [half*16, half*16+16) of particle k -----
        int k = blockIdx.x >> 1, half = blockIdx.x & 1;
        int gk = indexes[k];
        __shared__ float s_p[16][A_];
        __shared__ float s_part[16][16];

        if (tid < 64) {     // warps 0,1 fully active
            int tl = tid >> 2, a = tid & 3;
            int t = half*16 + tl;
            const float* e = embt + (size_t)(gk*T_ + t)*D_;
            float sum = 0.f;
            #pragma unroll 8
            for (int d = 0; d < D_; d++) sum += e[d] * Wstat[d*A_ + a];
            float m = fmaxf(sum, __shfl_xor_sync(0xffffffffu, sum, 1));
            m = fmaxf(m, __shfl_xor_sync(0xffffffffu, m, 2));
            float ex = __expf(sum - m);
            float ttl = ex + __shfl_xor_sync(0xffffffffu, ex, 1);
            ttl += __shfl_xor_sync(0xffffffffu, ttl, 2);
            s_p[tl][a] = ex / ttl;
        }
        __syncthreads();
        {
            int tl = tid >> 4, l16 = tid & 15;
            int t = half*16 + tl;
            float p0 = s_p[tl][0], p1 = s_p[tl][1], p2 = s_p[tl][2], p3 = s_p[tl][3];
            const float4* row = (const float4*)(lf + (size_t)(gk*T_ + t)*S_*A_);
            float acc = 0.f;
            #pragma unroll
            for (int g = 0; g < 2; g++) {          // 2 groups of 8 sites
                // batch all 8 loads first (MLP = 8)
                float4 v[8];
                #pragma unroll
                for (int i = 0; i < 8; i++) v[i] = row[l16 + 16*(g*8 + i)];
                float prodA = 1.f, prodB = 1.f;
                #pragma unroll
                for (int i = 0; i < 8; i += 2) {
                    float dA = p0*__expf(v[i].x)   + p1*__expf(v[i].y)
                             + p2*__expf(v[i].z)   + p3*__expf(v[i].w);
                    float dB = p0*__expf(v[i+1].x) + p1*__expf(v[i+1].y)
                             + p2*__expf(v[i+1].z) + p3*__expf(v[i+1].w);
                    prodA *= dA;
                    prodB *= dB;
                }
                acc += __logf(prodA * prodB);
            }
            s_part[tl][l16] = acc;
        }
        __syncthreads();
        if (tid < 16) {
            float c = 0.f;
            #pragma unroll
            for (int i = 0; i < 16; i++) c += s_part[tid][i];
            g_ckept[k*T_ + half*16 + tid] = c;
        }
    } else {
        // ----- kB candidate z -----
        int z = blockIdx.x - 2*K_;
        int k = z / J_;
        int gk = indexes[k];
        __shared__ float sP1[16], sP2[16], sstat[4];
        __shared__ float s_red[8];

        int i1 = idx1a[z], i2 = idx2a[z];
        float bb1 = br1[z], bb2 = br2[z];

        const float4* r1 = (const float4*)(lf + (size_t)(gk*T_ + i1)*S_*A_);
        const float4* r2 = (const float4*)(lf + (size_t)(gk*T_ + i2)*S_*A_);
        float4 w1 = r1[tid], w2 = r2[tid];
        float e10=__expf(w1.x), e11=__expf(w1.y), e12=__expf(w1.z), e13=__expf(w1.w);
        float e20=__expf(w2.x), e21=__expf(w2.y), e22=__expf(w2.z), e23=__expf(w2.w);

        if (warp == 0) {
            const float* emb = embJ + (size_t)z*D_;
            float logit = 0.f;
            if (lane < 20) {
                if (lane < 16) {
                    #pragma unroll 8
                    for (int d = 0; d < D_; d++) logit += emb[d] * Wq[d*16 + lane];
                } else {
                    int a = lane - 16;
                    #pragma unroll 8
                    for (int d = 0; d < D_; d++) logit += emb[d] * Wstat[d*A_ + a];
                }
            }
            {   // stat softmax (lanes 16..19); all lanes execute shuffles
                float mm = fmaxf(logit, __shfl_xor_sync(0xffffffffu, logit, 1));
                mm = fmaxf(mm, __shfl_xor_sync(0xffffffffu, mm, 2));
                float ex = __expf(logit - mm);
                float ttl = ex + __shfl_xor_sync(0xffffffffu, ex, 1);
                ttl += __shfl_xor_sync(0xffffffffu, ttl, 2);
                if (lane >= 16 && lane < 20) sstat[lane - 16] = ex / ttl;
            }
            int e = lane & 15, r = e >> 2, c = e & 3;
            float qoff = 0.f;
            if (lane < 16) {
                float x = logit;
                float sp = fmaxf(x, 0.f) + log1pf(__expf(-fabsf(x)));
                qoff = (r == c) ? 0.f : sp;
            }
            float s1 = qoff + __shfl_xor_sync(0xffffffffu, qoff, 1);
            float rs = s1 + __shfl_xor_sync(0xffffffffu, s1, 2);
            float Qown = (r == c) ? -rs : qoff;
            float Qe = __shfl_sync(0xffffffffu, Qown, lane & 15);

            // expm: lanes 0-15 -> P1, lanes 16-31 -> P2; fixed s=3, Taylor-7
            int base = lane & 16;
            float bsc = ((lane < 16) ? bb1 : bb2) * 0.125f;
            float Av = Qe * bsc;
            float Ev = Av + ((r == c) ? 1.f : 0.f);
            float Tm = Av;
            #pragma unroll
            for (int n = 2; n <= 7; n++) {
                float s = 0.f;
                #pragma unroll
                for (int j = 0; j < 4; j++) {
                    float trj = __shfl_sync(0xffffffffu, Tm, base + (r<<2) + j);
                    float ajc = __shfl_sync(0xffffffffu, Av, base + (j<<2) + c);
                    s += trj * ajc;
                }
                Tm = s * (1.f / (float)n);
                Ev += Tm;
            }
            #pragma unroll
            for (int qq = 0; qq < 3; qq++) {
                float s = 0.f;
                #pragma unroll
                for (int j = 0; j < 4; j++) {
                    float erj = __shfl_sync(0xffffffffu, Ev, base + (r<<2) + j);
                    float ejc = __shfl_sync(0xffffffffu, Ev, base + (j<<2) + c);
                    s += erj * ejc;
                }
                Ev = s;
            }
            Ev = fmaxf(Ev, 1e-30f);
            if (lane < 16) { sP1[e] = Ev; g_P1[z*16 + e] = Ev; }
            else           { sP2[e] = Ev; g_P2[z*16 + e] = Ev; }
        }
        __syncthreads();
        {
            float tot = 0.f;
            #pragma unroll
            for (int a = 0; a < 4; a++) {
                float m1 = sP1[a*4+0]*e10 + sP1[a*4+1]*e11 + sP1[a*4+2]*e12 + sP1[a*4+3]*e13;
                float m2 = sP2[a*4+0]*e20 + sP2[a*4+1]*e21 + sP2[a*4+2]*e22 + sP2[a*4+3]*e23;
                tot += m1 * m2 * sstat[a];
            }
            float val = __logf(tot);
            #pragma unroll
            for (int off = 16; off; off >>= 1)
                val += __shfl_down_sync(0xffffffffu, val, off);
            if (lane == 0) s_red[warp] = val;
        }
        __syncthreads();
        if (tid == 0) {
            float s = 0.f;
            #pragma unroll
            for (int w = 0; w < 8; w++) s += s_red[w];
            g_llnew[z] = s;
        }
    }
}

// ---------------- ksel: per-particle selection. grid = K, block = 32 ----------------
__global__ void __launch_bounds__(32) ksel(
        const int* __restrict__ indexes, const int* __restrict__ lc,
        const float* __restrict__ b1r, const float* __restrict__ b2r,
        const int* __restrict__ idx1a, const int* __restrict__ idx2a,
        const float* __restrict__ br1, const float* __restrict__ br2,
        const float* __restrict__ log_pi, const float* __restrict__ logvp,
        const float* __restrict__ gumbel, const float* __restrict__ logdf,
        float* __restrict__ out) {
    int k = blockIdx.x;
    int lane = threadIdx.x;
    int gk = indexes[k];

    float ck = g_ckept[k*T_ + lane];
    int l = lc[gk*T_ + lane];
    float fl = f_logdf(logdf, l);
    float cc = (l > 1) ? 1.f : 0.f;
    float sb = b1r[gk*R_ + lane] + b2r[gk*R_ + lane];
    #pragma unroll
    for (int off = 16; off; off >>= 1) {
        ck += __shfl_down_sync(0xffffffffu, ck, off);
        fl += __shfl_down_sync(0xffffffffu, fl, off);
        cc += __shfl_down_sync(0xffffffffu, cc, off);
        sb += __shfl_down_sync(0xffffffffu, sb, off);
    }
    float s_ct   = __shfl_sync(0xffffffffu, ck, 0);
    float s_flcT = __shfl_sync(0xffffffffu, fl, 0);
    float s_cT   = __shfl_sync(0xffffffffu, cc, 0);
    float s_sb   = __shfl_sync(0xffffffffu, sb, 0);

    float lw = -1e30f, lpn = 0.f, loglik = 0.f, gum = -1e30f;
    if (lane < J_) {
        int zc = k*J_ + lane;
        int c1 = idx1a[zc], c2 = idx2a[zc];
        loglik = s_ct - g_ckept[k*T_ + c1] - g_ckept[k*T_ + c2] + g_llnew[zc];
        float lbp = 2.f * (float)RP1 * LOG10F - 10.f * (s_sb + br1[zc] + br2[zc]);
        int l1 = lc[gk*T_ + c1], l2 = lc[gk*T_ + c2];
        float flcnew = s_flcT - f_logdf(logdf, l1) - f_logdf(logdf, l2)
                     + f_logdf(logdf, l1 + l2);
        float cnt = s_cT - (float)(l1 > 1) - (float)(l2 > 1) + 1.f;
        lpn = loglik + lbp - flcnew;
        lw = lpn - log_pi[gk] + __logf(cnt) - logvp[zc];
        gum = lw + gumbel[zc];
    }
    float m = lw;
    m = fmaxf(m, __shfl_xor_sync(0xffffffffu, m, 1));
    m = fmaxf(m, __shfl_xor_sync(0xffffffffu, m, 2));
    float ex = (lane < J_) ? __expf(lw - m) : 0.f;
    float se = ex + __shfl_xor_sync(0xffffffffu, ex, 1);
    se += __shfl_xor_sync(0xffffffffu, se, 2);

    // argmax computed redundantly on all lanes (warp-uniform shuffles)
    float g0 = __shfl_sync(0xffffffffu, gum, 0);
    float g1 = __shfl_sync(0xffffffffu, gum, 1);
    float g2 = __shfl_sync(0xffffffffu, gum, 2);
    float g3 = __shfl_sync(0xffffffffu, gum, 3);
    int best = 0; float bv = g0;
    if (g1 > bv) { bv = g1; best = 1; }
    if (g2 > bv) { bv = g2; best = 2; }
    if (g3 > bv) { bv = g3; best = 3; }
    float lpn_b  = __shfl_sync(0xffffffffu, lpn, best);
    float llik_b = __shfl_sync(0xffffffffu, loglik, best);

    if (lane == 0) {
        int zs = k*J_ + best;
        g_selinfo[k] = make_int4(gk, idx1a[zs], idx2a[zs], zs);
        out[O10 + k] = m + __logf(se) - LOG4F;
        out[O9 + k]  = lpn_b;
        out[O11 + k] = llik_b;
    }
}

// ---------------- Kernel 2: outputs. grid (9, K), block 256 ----------------
__global__ void __launch_bounds__(256, 8) k2(
        const int* __restrict__ lc, const int* __restrict__ hashes,
        const float* __restrict__ embt, const float* __restrict__ lf,
        const float* __restrict__ embJ,
        const float* __restrict__ br1, const float* __restrict__ br2,
        const int* __restrict__ m1r, const int* __restrict__ m2r,
        const float* __restrict__ b1r, const float* __restrict__ b2r,
        const float* __restrict__ embr,
        float* __restrict__ out) {
    int i = blockIdx.x;
    int k = blockIdx.y;
    int tid = threadIdx.x;
    int4 si = g_selinfo[k];
    int gk = si.x, i1 = si.y, i2 = si.z, zs = si.w;
    int a = min(i1, i2), b = max(i1, i2);

    if (i < 7) {
        int nbase = 4*i;
        int tt[4];
        #pragma unroll
        for (int r = 0; r < 4; r++) {
            int t = nbase + r;
            if (t >= a) t++;
            if (t >= b) t++;
            tt[r] = t;
        }
        {
            float4 v0 = ((const float4*)(lf + (size_t)(gk*T_ + tt[0])*S_*A_))[tid];
            float4 v1 = ((const float4*)(lf + (size_t)(gk*T_ + tt[1])*S_*A_))[tid];
            __stcs((float4*)(out + O8 + (size_t)(k*TM1 + nbase + 0)*S_*A_) + tid, v0);
            __stcs((float4*)(out + O8 + (size_t)(k*TM1 + nbase + 1)*S_*A_) + tid, v1);
        }
        {
            float4 v2 = ((const float4*)(lf + (size_t)(gk*T_ + tt[2])*S_*A_))[tid];
            float4 v3 = ((const float4*)(lf + (size_t)(gk*T_ + tt[3])*S_*A_))[tid];
            __stcs((float4*)(out + O8 + (size_t)(k*TM1 + nbase + 2)*S_*A_) + tid, v2);
            __stcs((float4*)(out + O8 + (size_t)(k*TM1 + nbase + 3)*S_*A_) + tid, v3);
        }
        {
            int r = tid >> 6, d = tid & 63;
            out[O7 + (size_t)(k*TM1 + nbase + r)*D_ + d] =
                embt[(size_t)(gk*T_ + tt[r])*D_ + d];
        }
        if (tid < 4) {
            out[O5 + k*TM1 + nbase + tid] = (float)lc[gk*T_ + tt[tid]];
            out[O6 + k*TM1 + nbase + tid] = (float)hashes[gk*T_ + tt[tid]];
        }
    } else if (i == 7) {
        __shared__ float sP1[16], sP2[16];
        if (tid < 16) sP1[tid] = g_P1[zs*16 + tid];
        else if (tid < 32) sP2[tid-16] = g_P2[zs*16 + tid - 16];
        int t0 = 28; if (t0 >= a) t0++; if (t0 >= b) t0++;
        int t1 = 29; if (t1 >= a) t1++; if (t1 >= b) t1++;
        {
            float4 v0 = ((const float4*)(lf + (size_t)(gk*T_ + t0)*S_*A_))[tid];
            float4 v1 = ((const float4*)(lf + (size_t)(gk*T_ + t1)*S_*A_))[tid];
            __stcs((float4*)(out + O8 + (size_t)(k*TM1 + 28)*S_*A_) + tid, v0);
            __stcs((float4*)(out + O8 + (size_t)(k*TM1 + 29)*S_*A_) + tid, v1);
        }
        float4 w1 = ((const float4*)(lf + (size_t)(gk*T_ + i1)*S_*A_))[tid];
        float4 w2 = ((const float4*)(lf + (size_t)(gk*T_ + i2)*S_*A_))[tid];
        __syncthreads();
        {
            float e10=__expf(w1.x), e11=__expf(w1.y), e12=__expf(w1.z), e13=__expf(w1.w);
            float e20=__expf(w2.x), e21=__expf(w2.y), e22=__expf(w2.z), e23=__expf(w2.w);
            float4 res;
            float* rp = (float*)&res;
            #pragma unroll
            for (int aa = 0; aa < 4; aa++) {
                float m1 = sP1[aa*4+0]*e10 + sP1[aa*4+1]*e11 + sP1[aa*4+2]*e12 + sP1[aa*4+3]*e13;
                float m2 = sP2[aa*4+0]*e20 + sP2[aa*4+1]*e21 + sP2[aa*4+2]*e22 + sP2[aa*4+3]*e23;
                rp[aa] = __logf(m1) + __logf(m2);
            }
            __stcs((float4*)(out + O8 + (size_t)(k*TM1 + 30)*S_*A_) + tid, res);
        }
        if (tid < 192) {
            int r = tid >> 6, d = tid & 63;
            float val;
            if (r < 2) {
                int t = (r == 0) ? t0 : t1;
                val = embt[(size_t)(gk*T_ + t)*D_ + d];
            } else {
                val = embJ[(size_t)zs*D_ + d];
            }
            out[O7 + (size_t)(k*TM1 + 28 + r)*D_ + d] = val;
        }
        if (tid < 2) {
            int t = (tid == 0) ? t0 : t1;
            out[O5 + k*TM1 + 28 + tid] = (float)lc[gk*T_ + t];
            out[O6 + k*TM1 + 28 + tid] = (float)hashes[gk*T_ + t];
        } else if (tid == 2) {
            int l1 = lc[gk*T_ + i1], l2 = lc[gk*T_ + i2];
            out[O5 + k*TM1 + 30] = (float)(l1 + l2);
            int h1 = hashes[gk*T_ + i1], h2 = hashes[gk*T_ + i2];
            int mn = min(h1, h2), mx = max(h1, h2);
            unsigned int hh = ((unsigned int)mn * 1000003u + (unsigned int)mx) * 40503u + 2531011u;
            out[O6 + k*TM1 + 30] = (float)(int)hh;
        }
    } else {
        if (tid < RP1) {
            int r = tid;
            float v1, v2, vb1, vb2;
            if (r < R_) {
                v1 = (float)m1r[gk*R_ + r];
                v2 = (float)m2r[gk*R_ + r];
                vb1 = b1r[gk*R_ + r];
                vb2 = b2r[gk*R_ + r];
            } else {
                v1 = (float)i1; v2 = (float)i2;
                vb1 = br1[zs];  vb2 = br2[zs];
            }
            out[O0 + k*RP1 + r] = v1;
            out[O1 + k*RP1 + r] = v2;
            out[O2 + k*RP1 + r] = vb1;
            out[O3 + k*RP1 + r] = vb2;
        }
        const float4* s4 = (const float4*)(embr + (size_t)gk*R_*D_);
        float4* d4 = (float4*)(out + O4 + (size_t)k*RP1*D_);
        d4[tid] = s4[tid];
        d4[tid + 256] = s4[tid + 256];
        if (tid < 16) {
            const float4* j4 = (const float4*)(embJ + (size_t)zs*D_);
            d4[512 + tid] = j4[tid];
        }
    }
}

// ---------------- launch ----------------
extern "C" void kernel_launch(void* const* d_in, const int* in_sizes, int n_in,
                              void* d_out, int out_size) {
    const int*   indexes = (const int*)  d_in[0];
    const int*   m1r     = (const int*)  d_in[1];
    const int*   m2r     = (const int*)  d_in[2];
    const float* b1r     = (const float*)d_in[3];
    const float* b2r     = (const float*)d_in[4];
    const float* embr    = (const float*)d_in[5];
    const int*   lc      = (const int*)  d_in[6];
    const int*   hashes  = (const int*)  d_in[7];
    const float* embt    = (const float*)d_in[8];
    const float* lf      = (const float*)d_in[9];
    const float* log_pi  = (const float*)d_in[10];
    const int*   idx1a   = (const int*)  d_in[11];
    const int*   idx2a   = (const int*)  d_in[12];
    const float* br1     = (const float*)d_in[13];
    const float* br2     = (const float*)d_in[14];
    const float* embJ    = (const float*)d_in[15];
    const float* logvp   = (const float*)d_in[16];
    const float* gumbel  = (const float*)d_in[17];
    const float* Wq      = (const float*)d_in[18];
    const float* Wstat   = (const float*)d_in[19];
    const float* logdf   = (const float*)d_in[20];
    float* out = (float*)d_out;

    k1<<<2*K_ + Z_, 256>>>(indexes, lc, embt, lf, Wstat,
                           idx1a, idx2a, br1, br2, embJ, Wq);
    ksel<<<K_, 32>>>(indexes, lc, b1r, b2r, idx1a, idx2a, br1, br2,
                     log_pi, logvp, gumbel, logdf, out);
    k2<<<dim3(9, K_), 256>>>(lc, hashes, embt, lf, embJ, br1, br2,
                             m1r, m2r, b1r, b2r, embr, out);
}

// round 9
// speedup vs baseline: 1.1199x; 1.1199x over previous
#include <cuda_runtime.h>
#include <cuda_bf16.h>
#include <math.h>

// Problem constants
#define K_ 128
#define J_ 4
#define N_ 64
#define R_ 32
#define T_ 32
#define S_ 256
#define A_ 4
#define D_ 64
#define Z_ (K_*J_)   // 512
#define TM1 (T_-1)   // 31
#define RP1 (R_+1)   // 33

// Output segment offsets (floats)
#define O0 0u
#define O1 4224u
#define O2 8448u
#define O3 12672u
#define O4 16896u
#define O5 287232u
#define O6 291200u
#define O7 295168u
#define O8 549120u
#define O9 4612352u
#define O10 4612480u
#define O11 4612608u

#define LOG10F 2.302585092994045684f
#define LOG4F  1.3862943611198906f

// ---------------- scratch ----------------
__device__ float g_ckept[K_*T_];
__device__ float g_llnew[Z_];
__device__ float g_P1[Z_*16];
__device__ float g_P2[Z_*16];
__device__ int4  g_selinfo[K_];   // {gk, i1, i2, zs}

__device__ __forceinline__ float f_logdf(const float* logdf, int l) {
    int di = 2*l - 3;
    di = max(0, min(2*N_ - 1, di));
    return logdf[di];
}

// ---------------- Kernel 1: kA quarters [0,4K) + kB candidates [4K,4K+Z) -----
// kA: ONE WARP = ONE lf ROW, fully autonomous (no smem, no __syncthreads).
__global__ void __launch_bounds__(256, 5) k1(
        const int* __restrict__ indexes,
        const int* __restrict__ lc, const float* __restrict__ embt,
        const float* __restrict__ lf, const float* __restrict__ Wstat,
        const int* __restrict__ idx1a, const int* __restrict__ idx2a,
        const float* __restrict__ br1, const float* __restrict__ br2,
        const float* __restrict__ embJ, const float* __restrict__ Wq) {
    int tid = threadIdx.x;
    int warp = tid >> 5, lane = tid & 31;

    if (blockIdx.x < 4*K_) {
        // ----- kA quarter: rows q*8 .. q*8+7, one row per warp -----
        int k = blockIdx.x >> 2, q = blockIdx.x & 3;
        int gk = indexes[k];
        int t = q*8 + warp;

        // logits: lane l covers d = 2l, 2l+1; butterfly-reduce 4 dots at once
        const float2* e2 = (const float2*)(embt + (size_t)(gk*T_ + t)*D_);
        float2 e = e2[lane];
        const float4* w4 = (const float4*)Wstat;     // Wstat[d][a] -> w4[d]
        float4 wa = w4[2*lane], wb = w4[2*lane + 1];
        float lg0 = e.x*wa.x + e.y*wb.x;
        float lg1 = e.x*wa.y + e.y*wb.y;
        float lg2 = e.x*wa.z + e.y*wb.z;
        float lg3 = e.x*wa.w + e.y*wb.w;
        #pragma unroll
        for (int off = 16; off; off >>= 1) {
            lg0 += __shfl_xor_sync(0xffffffffu, lg0, off);
            lg1 += __shfl_xor_sync(0xffffffffu, lg1, off);
            lg2 += __shfl_xor_sync(0xffffffffu, lg2, off);
            lg3 += __shfl_xor_sync(0xffffffffu, lg3, off);
        }
        // softmax (redundant per lane, in-register)
        float m = fmaxf(fmaxf(lg0, lg1), fmaxf(lg2, lg3));
        float p0 = __expf(lg0 - m), p1 = __expf(lg1 - m);
        float p2 = __expf(lg2 - m), p3 = __expf(lg3 - m);
        float inv = 1.f / (p0 + p1 + p2 + p3);
        p0 *= inv; p1 *= inv; p2 *= inv; p3 *= inv;

        // sites: lane handles s = lane + 32*i, i = 0..7 (two MLP=4 batches)
        const float4* row = (const float4*)(lf + (size_t)(gk*T_ + t)*S_*A_);
        float prodA = 1.f, prodB = 1.f;
        #pragma unroll
        for (int g = 0; g < 2; g++) {
            float4 v[4];
            #pragma unroll
            for (int i = 0; i < 4; i++) v[i] = row[lane + 32*(g*4 + i)];
            #pragma unroll
            for (int i = 0; i < 4; i += 2) {
                float dA = p0*__expf(v[i].x)   + p1*__expf(v[i].y)
                         + p2*__expf(v[i].z)   + p3*__expf(v[i].w);
                float dB = p0*__expf(v[i+1].x) + p1*__expf(v[i+1].y)
                         + p2*__expf(v[i+1].z) + p3*__expf(v[i+1].w);
                prodA *= dA;
                prodB *= dB;
            }
        }
        float acc = __logf(prodA * prodB);
        #pragma unroll
        for (int off = 16; off; off >>= 1)
            acc += __shfl_xor_sync(0xffffffffu, acc, off);
        if (lane == 0) g_ckept[k*T_ + t] = acc;
    } else {
        // ----- kB candidate z -----
        int z = blockIdx.x - 4*K_;
        int k = z / J_;
        int gk = indexes[k];
        __shared__ float sP1[16], sP2[16], sstat[4];
        __shared__ float s_red[8];

        int i1 = idx1a[z], i2 = idx2a[z];
        float bb1 = br1[z], bb2 = br2[z];

        const float4* r1 = (const float4*)(lf + (size_t)(gk*T_ + i1)*S_*A_);
        const float4* r2 = (const float4*)(lf + (size_t)(gk*T_ + i2)*S_*A_);
        float4 w1 = r1[tid], w2 = r2[tid];
        float e10=__expf(w1.x), e11=__expf(w1.y), e12=__expf(w1.z), e13=__expf(w1.w);
        float e20=__expf(w2.x), e21=__expf(w2.y), e22=__expf(w2.z), e23=__expf(w2.w);

        if (warp == 0) {
            const float* emb = embJ + (size_t)z*D_;
            float logit = 0.f;
            if (lane < 20) {
                if (lane < 16) {
                    #pragma unroll 8
                    for (int d = 0; d < D_; d++) logit += emb[d] * Wq[d*16 + lane];
                } else {
                    int a = lane - 16;
                    #pragma unroll 8
                    for (int d = 0; d < D_; d++) logit += emb[d] * Wstat[d*A_ + a];
                }
            }
            {   // stat softmax (lanes 16..19); all lanes execute shuffles
                float mm = fmaxf(logit, __shfl_xor_sync(0xffffffffu, logit, 1));
                mm = fmaxf(mm, __shfl_xor_sync(0xffffffffu, mm, 2));
                float ex = __expf(logit - mm);
                float ttl = ex + __shfl_xor_sync(0xffffffffu, ex, 1);
                ttl += __shfl_xor_sync(0xffffffffu, ttl, 2);
                if (lane >= 16 && lane < 20) sstat[lane - 16] = ex / ttl;
            }
            int e = lane & 15, r = e >> 2, c = e & 3;
            float qoff = 0.f;
            if (lane < 16) {
                float x = logit;
                float sp = fmaxf(x, 0.f) + log1pf(__expf(-fabsf(x)));
                qoff = (r == c) ? 0.f : sp;
            }
            float s1 = qoff + __shfl_xor_sync(0xffffffffu, qoff, 1);
            float rs = s1 + __shfl_xor_sync(0xffffffffu, s1, 2);
            float Qown = (r == c) ? -rs : qoff;
            float Qe = __shfl_sync(0xffffffffu, Qown, lane & 15);

            // expm: lanes 0-15 -> P1, lanes 16-31 -> P2; fixed s=3, Taylor-7
            int base = lane & 16;
            float bsc = ((lane < 16) ? bb1 : bb2) * 0.125f;
            float Av = Qe * bsc;
            float Ev = Av + ((r == c) ? 1.f : 0.f);
            float Tm = Av;
            #pragma unroll
            for (int n = 2; n <= 7; n++) {
                float s = 0.f;
                #pragma unroll
                for (int j = 0; j < 4; j++) {
                    float trj = __shfl_sync(0xffffffffu, Tm, base + (r<<2) + j);
                    float ajc = __shfl_sync(0xffffffffu, Av, base + (j<<2) + c);
                    s += trj * ajc;
                }
                Tm = s * (1.f / (float)n);
                Ev += Tm;
            }
            #pragma unroll
            for (int qq = 0; qq < 3; qq++) {
                float s = 0.f;
                #pragma unroll
                for (int j = 0; j < 4; j++) {
                    float erj = __shfl_sync(0xffffffffu, Ev, base + (r<<2) + j);
                    float ejc = __shfl_sync(0xffffffffu, Ev, base + (j<<2) + c);
                    s += erj * ejc;
                }
                Ev = s;
            }
            Ev = fmaxf(Ev, 1e-30f);
            if (lane < 16) { sP1[e] = Ev; g_P1[z*16 + e] = Ev; }
            else           { sP2[e] = Ev; g_P2[z*16 + e] = Ev; }
        }
        __syncthreads();
        {
            float tot = 0.f;
            #pragma unroll
            for (int a = 0; a < 4; a++) {
                float m1 = sP1[a*4+0]*e10 + sP1[a*4+1]*e11 + sP1[a*4+2]*e12 + sP1[a*4+3]*e13;
                float m2 = sP2[a*4+0]*e20 + sP2[a*4+1]*e21 + sP2[a*4+2]*e22 + sP2[a*4+3]*e23;
                tot += m1 * m2 * sstat[a];
            }
            float val = __logf(tot);
            #pragma unroll
            for (int off = 16; off; off >>= 1)
                val += __shfl_down_sync(0xffffffffu, val, off);
            if (lane == 0) s_red[warp] = val;
        }
        __syncthreads();
        if (tid == 0) {
            float s = 0.f;
            #pragma unroll
            for (int w = 0; w < 8; w++) s += s_red[w];
            g_llnew[z] = s;
        }
    }
}

// ---------------- ksel: per-particle selection. grid = K, block = 32 ----------------
__global__ void __launch_bounds__(32) ksel(
        const int* __restrict__ indexes, const int* __restrict__ lc,
        const float* __restrict__ b1r, const float* __restrict__ b2r,
        const int* __restrict__ idx1a, const int* __restrict__ idx2a,
        const float* __restrict__ br1, const float* __restrict__ br2,
        const float* __restrict__ log_pi, const float* __restrict__ logvp,
        const float* __restrict__ gumbel, const float* __restrict__ logdf,
        float* __restrict__ out) {
    int k = blockIdx.x;
    int lane = threadIdx.x;
    int gk = indexes[k];

    float ck = g_ckept[k*T_ + lane];
    int l = lc[gk*T_ + lane];
    float fl = f_logdf(logdf, l);
    float cc = (l > 1) ? 1.f : 0.f;
    float sb = b1r[gk*R_ + lane] + b2r[gk*R_ + lane];
    #pragma unroll
    for (int off = 16; off; off >>= 1) {
        ck += __shfl_down_sync(0xffffffffu, ck, off);
        fl += __shfl_down_sync(0xffffffffu, fl, off);
        cc += __shfl_down_sync(0xffffffffu, cc, off);
        sb += __shfl_down_sync(0xffffffffu, sb, off);
    }
    float s_ct   = __shfl_sync(0xffffffffu, ck, 0);
    float s_flcT = __shfl_sync(0xffffffffu, fl, 0);
    float s_cT   = __shfl_sync(0xffffffffu, cc, 0);
    float s_sb   = __shfl_sync(0xffffffffu, sb, 0);

    float lw = -1e30f, lpn = 0.f, loglik = 0.f, gum = -1e30f;
    if (lane < J_) {
        int zc = k*J_ + lane;
        int c1 = idx1a[zc], c2 = idx2a[zc];
        loglik = s_ct - g_ckept[k*T_ + c1] - g_ckept[k*T_ + c2] + g_llnew[zc];
        float lbp = 2.f * (float)RP1 * LOG10F - 10.f * (s_sb + br1[zc] + br2[zc]);
        int l1 = lc[gk*T_ + c1], l2 = lc[gk*T_ + c2];
        float flcnew = s_flcT - f_logdf(logdf, l1) - f_logdf(logdf, l2)
                     + f_logdf(logdf, l1 + l2);
        float cnt = s_cT - (float)(l1 > 1) - (float)(l2 > 1) + 1.f;
        lpn = loglik + lbp - flcnew;
        lw = lpn - log_pi[gk] + __logf(cnt) - logvp[zc];
        gum = lw + gumbel[zc];
    }
    float m = lw;
    m = fmaxf(m, __shfl_xor_sync(0xffffffffu, m, 1));
    m = fmaxf(m, __shfl_xor_sync(0xffffffffu, m, 2));
    float ex = (lane < J_) ? __expf(lw - m) : 0.f;
    float se = ex + __shfl_xor_sync(0xffffffffu, ex, 1);
    se += __shfl_xor_sync(0xffffffffu, se, 2);

    // argmax computed redundantly on all lanes (warp-uniform shuffles)
    float g0 = __shfl_sync(0xffffffffu, gum, 0);
    float g1 = __shfl_sync(0xffffffffu, gum, 1);
    float g2 = __shfl_sync(0xffffffffu, gum, 2);
    float g3 = __shfl_sync(0xffffffffu, gum, 3);
    int best = 0; float bv = g0;
    if (g1 > bv) { bv = g1; best = 1; }
    if (g2 > bv) { bv = g2; best = 2; }
    if (g3 > bv) { bv = g3; best = 3; }
    float lpn_b  = __shfl_sync(0xffffffffu, lpn, best);
    float llik_b = __shfl_sync(0xffffffffu, loglik, best);

    if (lane == 0) {
        int zs = k*J_ + best;
        g_selinfo[k] = make_int4(gk, idx1a[zs], idx2a[zs], zs);
        out[O10 + k] = m + __logf(se) - LOG4F;
        out[O9 + k]  = lpn_b;
        out[O11 + k] = llik_b;
    }
}

// ---------------- Kernel 2: outputs. grid (9, K), block 256 ----------------
__global__ void __launch_bounds__(256, 8) k2(
        const int* __restrict__ lc, const int* __restrict__ hashes,
        const float* __restrict__ embt, const float* __restrict__ lf,
        const float* __restrict__ embJ,
        const float* __restrict__ br1, const float* __restrict__ br2,
        const int* __restrict__ m1r, const int* __restrict__ m2r,
        const float* __restrict__ b1r, const float* __restrict__ b2r,
        const float* __restrict__ embr,
        float* __restrict__ out) {
    int i = blockIdx.x;
    int k = blockIdx.y;
    int tid = threadIdx.x;
    int4 si = g_selinfo[k];
    int gk = si.x, i1 = si.y, i2 = si.z, zs = si.w;
    int a = min(i1, i2), b = max(i1, i2);

    if (i < 7) {
        int nbase = 4*i;
        int tt[4];
        #pragma unroll
        for (int r = 0; r < 4; r++) {
            int t = nbase + r;
            if (t >= a) t++;
            if (t >= b) t++;
            tt[r] = t;
        }
        {
            float4 v0 = ((const float4*)(lf + (size_t)(gk*T_ + tt[0])*S_*A_))[tid];
            float4 v1 = ((const float4*)(lf + (size_t)(gk*T_ + tt[1])*S_*A_))[tid];
            __stcs((float4*)(out + O8 + (size_t)(k*TM1 + nbase + 0)*S_*A_) + tid, v0);
            __stcs((float4*)(out + O8 + (size_t)(k*TM1 + nbase + 1)*S_*A_) + tid, v1);
        }
        {
            float4 v2 = ((const float4*)(lf + (size_t)(gk*T_ + tt[2])*S_*A_))[tid];
            float4 v3 = ((const float4*)(lf + (size_t)(gk*T_ + tt[3])*S_*A_))[tid];
            __stcs((float4*)(out + O8 + (size_t)(k*TM1 + nbase + 2)*S_*A_) + tid, v2);
            __stcs((float4*)(out + O8 + (size_t)(k*TM1 + nbase + 3)*S_*A_) + tid, v3);
        }
        {
            int r = tid >> 6, d = tid & 63;
            out[O7 + (size_t)(k*TM1 + nbase + r)*D_ + d] =
                embt[(size_t)(gk*T_ + tt[r])*D_ + d];
        }
        if (tid < 4) {
            out[O5 + k*TM1 + nbase + tid] = (float)lc[gk*T_ + tt[tid]];
            out[O6 + k*TM1 + nbase + tid] = (float)hashes[gk*T_ + tt[tid]];
        }
    } else if (i == 7) {
        __shared__ float sP1[16], sP2[16];
        if (tid < 16) sP1[tid] = g_P1[zs*16 + tid];
        else if (tid < 32) sP2[tid-16] = g_P2[zs*16 + tid - 16];
        int t0 = 28; if (t0 >= a) t0++; if (t0 >= b) t0++;
        int t1 = 29; if (t1 >= a) t1++; if (t1 >= b) t1++;
        {
            float4 v0 = ((const float4*)(lf + (size_t)(gk*T_ + t0)*S_*A_))[tid];
            float4 v1 = ((const float4*)(lf + (size_t)(gk*T_ + t1)*S_*A_))[tid];
            __stcs((float4*)(out + O8 + (size_t)(k*TM1 + 28)*S_*A_) + tid, v0);
            __stcs((float4*)(out + O8 + (size_t)(k*TM1 + 29)*S_*A_) + tid, v1);
        }
        float4 w1 = ((const float4*)(lf + (size_t)(gk*T_ + i1)*S_*A_))[tid];
        float4 w2 = ((const float4*)(lf + (size_t)(gk*T_ + i2)*S_*A_))[tid];
        __syncthreads();
        {
            float e10=__expf(w1.x), e11=__expf(w1.y), e12=__expf(w1.z), e13=__expf(w1.w);
            float e20=__expf(w2.x), e21=__expf(w2.y), e22=__expf(w2.z), e23=__expf(w2.w);
            float4 res;
            float* rp = (float*)&res;
            #pragma unroll
            for (int aa = 0; aa < 4; aa++) {
                float m1 = sP1[aa*4+0]*e10 + sP1[aa*4+1]*e11 + sP1[aa*4+2]*e12 + sP1[aa*4+3]*e13;
                float m2 = sP2[aa*4+0]*e20 + sP2[aa*4+1]*e21 + sP2[aa*4+2]*e22 + sP2[aa*4+3]*e23;
                rp[aa] = __logf(m1) + __logf(m2);
            }
            __stcs((float4*)(out + O8 + (size_t)(k*TM1 + 30)*S_*A_) + tid, res);
        }
        if (tid < 192) {
            int r = tid >> 6, d = tid & 63;
            float val;
            if (r < 2) {
                int t = (r == 0) ? t0 : t1;
                val = embt[(size_t)(gk*T_ + t)*D_ + d];
            } else {
                val = embJ[(size_t)zs*D_ + d];
            }
            out[O7 + (size_t)(k*TM1 + 28 + r)*D_ + d] = val;
        }
        if (tid < 2) {
            int t = (tid == 0) ? t0 : t1;
            out[O5 + k*TM1 + 28 + tid] = (float)lc[gk*T_ + t];
            out[O6 + k*TM1 + 28 + tid] = (float)hashes[gk*T_ + t];
        } else if (tid == 2) {
            int l1 = lc[gk*T_ + i1], l2 = lc[gk*T_ + i2];
            out[O5 + k*TM1 + 30] = (float)(l1 + l2);
            int h1 = hashes[gk*T_ + i1], h2 = hashes[gk*T_ + i2];
            int mn = min(h1, h2), mx = max(h1, h2);
            unsigned int hh = ((unsigned int)mn * 1000003u + (unsigned int)mx) * 40503u + 2531011u;
            out[O6 + k*TM1 + 30] = (float)(int)hh;
        }
    } else {
        if (tid < RP1) {
            int r = tid;
            float v1, v2, vb1, vb2;
            if (r < R_) {
                v1 = (float)m1r[gk*R_ + r];
                v2 = (float)m2r[gk*R_ + r];
                vb1 = b1r[gk*R_ + r];
                vb2 = b2r[gk*R_ + r];
            } else {
                v1 = (float)i1; v2 = (float)i2;
                vb1 = br1[zs];  vb2 = br2[zs];
            }
            out[O0 + k*RP1 + r] = v1;
            out[O1 + k*RP1 + r] = v2;
            out[O2 + k*RP1 + r] = vb1;
            out[O3 + k*RP1 + r] = vb2;
        }
        const float4* s4 = (const float4*)(embr + (size_t)gk*R_*D_);
        float4* d4 = (float4*)(out + O4 + (size_t)k*RP1*D_);
        d4[tid] = s4[tid];
        d4[tid + 256] = s4[tid + 256];
        if (tid < 16) {
            const float4* j4 = (const float4*)(embJ + (size_t)zs*D_);
            d4[512 + tid] = j4[tid];
        }
    }
}

// ---------------- launch ----------------
extern "C" void kernel_launch(void* const* d_in, const int* in_sizes, int n_in,
                              void* d_out, int out_size) {
    const int*   indexes = (const int*)  d_in[0];
    const int*   m1r     = (const int*)  d_in[1];
    const int*   m2r     = (const int*)  d_in[2];
    const float* b1r     = (const float*)d_in[3];
    const float* b2r     = (const float*)d_in[4];
    const float* embr    = (const float*)d_in[5];
    const int*   lc      = (const int*)  d_in[6];
    const int*   hashes  = (const int*)  d_in[7];
    const float* embt    = (const float*)d_in[8];
    const float* lf      = (const float*)d_in[9];
    const float* log_pi  = (const float*)d_in[10];
    const int*   idx1a   = (const int*)  d_in[11];
    const int*   idx2a   = (const int*)  d_in[12];
    const float* br1     = (const float*)d_in[13];
    const float* br2     = (const float*)d_in[14];
    const float* embJ    = (const float*)d_in[15];
    const float* logvp   = (const float*)d_in[16];
    const float* gumbel  = (const float*)d_in[17];
    const float* Wq      = (const float*)d_in[18];
    const float* Wstat   = (const float*)d_in[19];
    const float* logdf   = (const float*)d_in[20];
    float* out = (float*)d_out;

    k1<<<4*K_ + Z_, 256>>>(indexes, lc, embt, lf, Wstat,
                           idx1a, idx2a, br1, br2, embJ, Wq);
    ksel<<<K_, 32>>>(indexes, lc, b1r, b2r, idx1a, idx2a, br1, br2,
                     log_pi, logvp, gumbel, logdf, out);
    k2<<<dim3(9, K_), 256>>>(lc, hashes, embt, lf, embJ, br1, br2,
                             m1r, m2r, b1r, b2r, embr, out);
}

// round 10
// speedup vs baseline: 1.1218x; 1.0017x over previous
#include <cuda_runtime.h>
#include <cuda_bf16.h>
#include <math.h>

// Problem constants
#define K_ 128
#define J_ 4
#define N_ 64
#define R_ 32
#define T_ 32
#define S_ 256
#define A_ 4
#define D_ 64
#define Z_ (K_*J_)   // 512
#define TM1 (T_-1)   // 31
#define RP1 (R_+1)   // 33

// Output segment offsets (floats)
#define O0 0u
#define O1 4224u
#define O2 8448u
#define O3 12672u
#define O4 16896u
#define O5 287232u
#define O6 291200u
#define O7 295168u
#define O8 549120u
#define O9 4612352u
#define O10 4612480u
#define O11 4612608u

#define LOG10F 2.302585092994045684f
#define LOG4F  1.3862943611198906f

// ---------------- scratch ----------------
__device__ float g_ckept[K_*T_];
__device__ float g_llnew[Z_];
__device__ float g_P1[Z_*16];
__device__ float g_P2[Z_*16];
__device__ int4  g_selinfo[K_];   // {gk, i1, i2, zs}

__device__ __forceinline__ float f_logdf(const float* logdf, int l) {
    int di = 2*l - 3;
    di = max(0, min(2*N_ - 1, di));
    return logdf[di];
}

// ---------------- Kernel 1: kA quarters [0,4K) + kB candidates [4K,4K+Z) -----
__global__ void __launch_bounds__(256, 5) k1(
        const int* __restrict__ indexes,
        const int* __restrict__ lc, const float* __restrict__ embt,
        const float* __restrict__ lf, const float* __restrict__ Wstat,
        const int* __restrict__ idx1a, const int* __restrict__ idx2a,
        const float* __restrict__ br1, const float* __restrict__ br2,
        const float* __restrict__ embJ, const float* __restrict__ Wq) {
    int tid = threadIdx.x;
    int warp = tid >> 5, lane = tid & 31;

    if (blockIdx.x < 4*K_) {
        // ----- kA quarter: rows q*8 .. q*8+7, one row per warp (autonomous) -----
        int k = blockIdx.x >> 2, q = blockIdx.x & 3;
        int gk = indexes[k];
        int t = q*8 + warp;

        const float2* e2 = (const float2*)(embt + (size_t)(gk*T_ + t)*D_);
        float2 e = e2[lane];
        const float4* w4 = (const float4*)Wstat;
        float4 wa = w4[2*lane], wb = w4[2*lane + 1];
        float lg0 = e.x*wa.x + e.y*wb.x;
        float lg1 = e.x*wa.y + e.y*wb.y;
        float lg2 = e.x*wa.z + e.y*wb.z;
        float lg3 = e.x*wa.w + e.y*wb.w;
        #pragma unroll
        for (int off = 16; off; off >>= 1) {
            lg0 += __shfl_xor_sync(0xffffffffu, lg0, off);
            lg1 += __shfl_xor_sync(0xffffffffu, lg1, off);
            lg2 += __shfl_xor_sync(0xffffffffu, lg2, off);
            lg3 += __shfl_xor_sync(0xffffffffu, lg3, off);
        }
        float m = fmaxf(fmaxf(lg0, lg1), fmaxf(lg2, lg3));
        float p0 = __expf(lg0 - m), p1 = __expf(lg1 - m);
        float p2 = __expf(lg2 - m), p3 = __expf(lg3 - m);
        float inv = 1.f / (p0 + p1 + p2 + p3);
        p0 *= inv; p1 *= inv; p2 *= inv; p3 *= inv;

        const float4* row = (const float4*)(lf + (size_t)(gk*T_ + t)*S_*A_);
        float prodA = 1.f, prodB = 1.f;
        #pragma unroll
        for (int g = 0; g < 2; g++) {
            float4 v[4];
            #pragma unroll
            for (int i = 0; i < 4; i++) v[i] = row[lane + 32*(g*4 + i)];
            #pragma unroll
            for (int i = 0; i < 4; i += 2) {
                float dA = p0*__expf(v[i].x)   + p1*__expf(v[i].y)
                         + p2*__expf(v[i].z)   + p3*__expf(v[i].w);
                float dB = p0*__expf(v[i+1].x) + p1*__expf(v[i+1].y)
                         + p2*__expf(v[i+1].z) + p3*__expf(v[i+1].w);
                prodA *= dA;
                prodB *= dB;
            }
        }
        float acc = __logf(prodA * prodB);
        #pragma unroll
        for (int off = 16; off; off >>= 1)
            acc += __shfl_xor_sync(0xffffffffu, acc, off);
        if (lane == 0) g_ckept[k*T_ + t] = acc;
    } else {
        // ----- kB candidate z -----
        int z = blockIdx.x - 4*K_;
        int k = z / J_;
        int gk = indexes[k];
        __shared__ float sQ[16];
        __shared__ float sP1[16], sP2[16], sstat[4];
        __shared__ float s_red[8];

        int i1 = idx1a[z], i2 = idx2a[z];
        float bb1 = br1[z], bb2 = br2[z];

        const float4* r1 = (const float4*)(lf + (size_t)(gk*T_ + i1)*S_*A_);
        const float4* r2 = (const float4*)(lf + (size_t)(gk*T_ + i2)*S_*A_);
        float4 w1 = r1[tid], w2 = r2[tid];
        float e10=__expf(w1.x), e11=__expf(w1.y), e12=__expf(w1.z), e13=__expf(w1.w);
        float e20=__expf(w2.x), e21=__expf(w2.y), e22=__expf(w2.z), e23=__expf(w2.w);

        if (warp == 0) {
            const float* emb = embJ + (size_t)z*D_;
            float logit = 0.f;
            if (lane < 20) {
                if (lane < 16) {
                    #pragma unroll 8
                    for (int d = 0; d < D_; d++) logit += emb[d] * Wq[d*16 + lane];
                } else {
                    int a = lane - 16;
                    #pragma unroll 8
                    for (int d = 0; d < D_; d++) logit += emb[d] * Wstat[d*A_ + a];
                }
            }
            {   // stat softmax (lanes 16..19); all lanes execute shuffles
                float mm = fmaxf(logit, __shfl_xor_sync(0xffffffffu, logit, 1));
                mm = fmaxf(mm, __shfl_xor_sync(0xffffffffu, mm, 2));
                float ex = __expf(logit - mm);
                float ttl = ex + __shfl_xor_sync(0xffffffffu, ex, 1);
                ttl += __shfl_xor_sync(0xffffffffu, ttl, 2);
                if (lane >= 16 && lane < 20) sstat[lane - 16] = ex / ttl;
            }
            // Q matrix -> sQ (lanes 0..15 own element e)
            int e = lane & 15, r = e >> 2, c = e & 3;
            float qoff = 0.f;
            if (lane < 16) {
                float x = logit;
                float sp = fmaxf(x, 0.f) + log1pf(__expf(-fabsf(x)));
                qoff = (r == c) ? 0.f : sp;
            }
            float s1 = qoff + __shfl_xor_sync(0xffffffffu, qoff, 1);
            float rs = s1 + __shfl_xor_sync(0xffffffffu, s1, 2);
            float Qown = (r == c) ? -rs : qoff;
            if (lane < 16) sQ[e] = Qown;
            __syncwarp();

            // expm: lanes 0-7 (4 lanes per matrix, one row each, full A in regs).
            // Taylor-7 iterations are communication-free; only 3 squarings shuffle.
            if (lane < 8) {
                int mat = lane >> 2;          // 0 -> P1, 1 -> P2
                int row = lane & 3;
                float bsc = ((mat == 0) ? bb1 : bb2) * 0.125f;
                float Am[16];
                #pragma unroll
                for (int i = 0; i < 16; i++) Am[i] = sQ[i] * bsc;
                float E[4], Tm[4];
                #pragma unroll
                for (int cc = 0; cc < 4; cc++) {
                    Tm[cc] = Am[row*4 + cc];
                    E[cc]  = Tm[cc] + ((row == cc) ? 1.f : 0.f);
                }
                #pragma unroll
                for (int n = 2; n <= 7; n++) {
                    float invn = 1.f / (float)n;
                    float Tn[4];
                    #pragma unroll
                    for (int cc = 0; cc < 4; cc++)
                        Tn[cc] = (Tm[0]*Am[0*4+cc] + Tm[1]*Am[1*4+cc]
                                + Tm[2]*Am[2*4+cc] + Tm[3]*Am[3*4+cc]) * invn;
                    #pragma unroll
                    for (int cc = 0; cc < 4; cc++) { Tm[cc] = Tn[cc]; E[cc] += Tn[cc]; }
                }
                int base = lane & 4;          // group base: 0 or 4
                #pragma unroll
                for (int qq = 0; qq < 3; qq++) {
                    float En[4] = {0.f, 0.f, 0.f, 0.f};
                    #pragma unroll
                    for (int j = 0; j < 4; j++) {
                        float o0 = __shfl_sync(0xFFu, E[0], base + j);
                        float o1 = __shfl_sync(0xFFu, E[1], base + j);
                        float o2 = __shfl_sync(0xFFu, E[2], base + j);
                        float o3 = __shfl_sync(0xFFu, E[3], base + j);
                        En[0] = fmaf(E[j], o0, En[0]);
                        En[1] = fmaf(E[j], o1, En[1]);
                        En[2] = fmaf(E[j], o2, En[2]);
                        En[3] = fmaf(E[j], o3, En[3]);
                    }
                    #pragma unroll
                    for (int cc = 0; cc < 4; cc++) E[cc] = En[cc];
                }
                float* sP = (mat == 0) ? sP1 : sP2;
                float* gP = (mat == 0) ? (g_P1 + z*16) : (g_P2 + z*16);
                #pragma unroll
                for (int cc = 0; cc < 4; cc++) {
                    float val = fmaxf(E[cc], 1e-30f);
                    sP[row*4 + cc] = val;
                    gP[row*4 + cc] = val;
                }
            }
        }
        __syncthreads();
        {
            float tot = 0.f;
            #pragma unroll
            for (int a = 0; a < 4; a++) {
                float m1 = sP1[a*4+0]*e10 + sP1[a*4+1]*e11 + sP1[a*4+2]*e12 + sP1[a*4+3]*e13;
                float m2 = sP2[a*4+0]*e20 + sP2[a*4+1]*e21 + sP2[a*4+2]*e22 + sP2[a*4+3]*e23;
                tot += m1 * m2 * sstat[a];
            }
            float val = __logf(tot);
            #pragma unroll
            for (int off = 16; off; off >>= 1)
                val += __shfl_down_sync(0xffffffffu, val, off);
            if (lane == 0) s_red[warp] = val;
        }
        __syncthreads();
        if (tid == 0) {
            float s = 0.f;
            #pragma unroll
            for (int w = 0; w < 8; w++) s += s_red[w];
            g_llnew[z] = s;
        }
    }
}

// ---------------- ksel: per-particle selection. grid = K, block = 32 ----------------
__global__ void __launch_bounds__(32) ksel(
        const int* __restrict__ indexes, const int* __restrict__ lc,
        const float* __restrict__ b1r, const float* __restrict__ b2r,
        const int* __restrict__ idx1a, const int* __restrict__ idx2a,
        const float* __restrict__ br1, const float* __restrict__ br2,
        const float* __restrict__ log_pi, const float* __restrict__ logvp,
        const float* __restrict__ gumbel, const float* __restrict__ logdf,
        float* __restrict__ out) {
    int k = blockIdx.x;
    int lane = threadIdx.x;
    int gk = indexes[k];

    float ck = g_ckept[k*T_ + lane];
    int l = lc[gk*T_ + lane];
    float fl = f_logdf(logdf, l);
    float cc = (l > 1) ? 1.f : 0.f;
    float sb = b1r[gk*R_ + lane] + b2r[gk*R_ + lane];
    #pragma unroll
    for (int off = 16; off; off >>= 1) {
        ck += __shfl_down_sync(0xffffffffu, ck, off);
        fl += __shfl_down_sync(0xffffffffu, fl, off);
        cc += __shfl_down_sync(0xffffffffu, cc, off);
        sb += __shfl_down_sync(0xffffffffu, sb, off);
    }
    float s_ct   = __shfl_sync(0xffffffffu, ck, 0);
    float s_flcT = __shfl_sync(0xffffffffu, fl, 0);
    float s_cT   = __shfl_sync(0xffffffffu, cc, 0);
    float s_sb   = __shfl_sync(0xffffffffu, sb, 0);

    float lw = -1e30f, lpn = 0.f, loglik = 0.f, gum = -1e30f;
    if (lane < J_) {
        int zc = k*J_ + lane;
        int c1 = idx1a[zc], c2 = idx2a[zc];
        loglik = s_ct - g_ckept[k*T_ + c1] - g_ckept[k*T_ + c2] + g_llnew[zc];
        float lbp = 2.f * (float)RP1 * LOG10F - 10.f * (s_sb + br1[zc] + br2[zc]);
        int l1 = lc[gk*T_ + c1], l2 = lc[gk*T_ + c2];
        float flcnew = s_flcT - f_logdf(logdf, l1) - f_logdf(logdf, l2)
                     + f_logdf(logdf, l1 + l2);
        float cnt = s_cT - (float)(l1 > 1) - (float)(l2 > 1) + 1.f;
        lpn = loglik + lbp - flcnew;
        lw = lpn - log_pi[gk] + __logf(cnt) - logvp[zc];
        gum = lw + gumbel[zc];
    }
    float m = lw;
    m = fmaxf(m, __shfl_xor_sync(0xffffffffu, m, 1));
    m = fmaxf(m, __shfl_xor_sync(0xffffffffu, m, 2));
    float ex = (lane < J_) ? __expf(lw - m) : 0.f;
    float se = ex + __shfl_xor_sync(0xffffffffu, ex, 1);
    se += __shfl_xor_sync(0xffffffffu, se, 2);

    float g0 = __shfl_sync(0xffffffffu, gum, 0);
    float g1 = __shfl_sync(0xffffffffu, gum, 1);
    float g2 = __shfl_sync(0xffffffffu, gum, 2);
    float g3 = __shfl_sync(0xffffffffu, gum, 3);
    int best = 0; float bv = g0;
    if (g1 > bv) { bv = g1; best = 1; }
    if (g2 > bv) { bv = g2; best = 2; }
    if (g3 > bv) { bv = g3; best = 3; }
    float lpn_b  = __shfl_sync(0xffffffffu, lpn, best);
    float llik_b = __shfl_sync(0xffffffffu, loglik, best);

    if (lane == 0) {
        int zs = k*J_ + best;
        g_selinfo[k] = make_int4(gk, idx1a[zs], idx2a[zs], zs);
        out[O10 + k] = m + __logf(se) - LOG4F;
        out[O9 + k]  = lpn_b;
        out[O11 + k] = llik_b;
    }
}

// ---------------- Kernel 2: outputs. grid (9, K), block 256 ----------------
__global__ void __launch_bounds__(256, 8) k2(
        const int* __restrict__ lc, const int* __restrict__ hashes,
        const float* __restrict__ embt, const float* __restrict__ lf,
        const float* __restrict__ embJ,
        const float* __restrict__ br1, const float* __restrict__ br2,
        const int* __restrict__ m1r, const int* __restrict__ m2r,
        const float* __restrict__ b1r, const float* __restrict__ b2r,
        const float* __restrict__ embr,
        float* __restrict__ out) {
    int i = blockIdx.x;
    int k = blockIdx.y;
    int tid = threadIdx.x;
    int4 si = g_selinfo[k];
    int gk = si.x, i1 = si.y, i2 = si.z, zs = si.w;
    int a = min(i1, i2), b = max(i1, i2);

    if (i < 7) {
        int nbase = 4*i;
        int tt[4];
        #pragma unroll
        for (int r = 0; r < 4; r++) {
            int t = nbase + r;
            if (t >= a) t++;
            if (t >= b) t++;
            tt[r] = t;
        }
        {
            float4 v0 = ((const float4*)(lf + (size_t)(gk*T_ + tt[0])*S_*A_))[tid];
            float4 v1 = ((const float4*)(lf + (size_t)(gk*T_ + tt[1])*S_*A_))[tid];
            __stcs((float4*)(out + O8 + (size_t)(k*TM1 + nbase + 0)*S_*A_) + tid, v0);
            __stcs((float4*)(out + O8 + (size_t)(k*TM1 + nbase + 1)*S_*A_) + tid, v1);
        }
        {
            float4 v2 = ((const float4*)(lf + (size_t)(gk*T_ + tt[2])*S_*A_))[tid];
            float4 v3 = ((const float4*)(lf + (size_t)(gk*T_ + tt[3])*S_*A_))[tid];
            __stcs((float4*)(out + O8 + (size_t)(k*TM1 + nbase + 2)*S_*A_) + tid, v2);
            __stcs((float4*)(out + O8 + (size_t)(k*TM1 + nbase + 3)*S_*A_) + tid, v3);
        }
        {
            int r = tid >> 6, d = tid & 63;
            out[O7 + (size_t)(k*TM1 + nbase + r)*D_ + d] =
                embt[(size_t)(gk*T_ + tt[r])*D_ + d];
        }
        if (tid < 4) {
            out[O5 + k*TM1 + nbase + tid] = (float)lc[gk*T_ + tt[tid]];
            out[O6 + k*TM1 + nbase + tid] = (float)hashes[gk*T_ + tt[tid]];
        }
    } else if (i == 7) {
        __shared__ float sP1[16], sP2[16];
        if (tid < 16) sP1[tid] = g_P1[zs*16 + tid];
        else if (tid < 32) sP2[tid-16] = g_P2[zs*16 + tid - 16];
        int t0 = 28; if (t0 >= a) t0++; if (t0 >= b) t0++;
        int t1 = 29; if (t1 >= a) t1++; if (t1 >= b) t1++;
        {
            float4 v0 = ((const float4*)(lf + (size_t)(gk*T_ + t0)*S_*A_))[tid];
            float4 v1 = ((const float4*)(lf + (size_t)(gk*T_ + t1)*S_*A_))[tid];
            __stcs((float4*)(out + O8 + (size_t)(k*TM1 + 28)*S_*A_) + tid, v0);
            __stcs((float4*)(out + O8 + (size_t)(k*TM1 + 29)*S_*A_) + tid, v1);
        }
        float4 w1 = ((const float4*)(lf + (size_t)(gk*T_ + i1)*S_*A_))[tid];
        float4 w2 = ((const float4*)(lf + (size_t)(gk*T_ + i2)*S_*A_))[tid];
        __syncthreads();
        {
            float e10=__expf(w1.x), e11=__expf(w1.y), e12=__expf(w1.z), e13=__expf(w1.w);
            float e20=__expf(w2.x), e21=__expf(w2.y), e22=__expf(w2.z), e23=__expf(w2.w);
            float4 res;
            float* rp = (float*)&res;
            #pragma unroll
            for (int aa = 0; aa < 4; aa++) {
                float m1 = sP1[aa*4+0]*e10 + sP1[aa*4+1]*e11 + sP1[aa*4+2]*e12 + sP1[aa*4+3]*e13;
                float m2 = sP2[aa*4+0]*e20 + sP2[aa*4+1]*e21 + sP2[aa*4+2]*e22 + sP2[aa*4+3]*e23;
                rp[aa] = __logf(m1) + __logf(m2);
            }
            __stcs((float4*)(out + O8 + (size_t)(k*TM1 + 30)*S_*A_) + tid, res);
        }
        if (tid < 192) {
            int r = tid >> 6, d = tid & 63;
            float val;
            if (r < 2) {
                int t = (r == 0) ? t0 : t1;
                val = embt[(size_t)(gk*T_ + t)*D_ + d];
            } else {
                val = embJ[(size_t)zs*D_ + d];
            }
            out[O7 + (size_t)(k*TM1 + 28 + r)*D_ + d] = val;
        }
        if (tid < 2) {
            int t = (tid == 0) ? t0 : t1;
            out[O5 + k*TM1 + 28 + tid] = (float)lc[gk*T_ + t];
            out[O6 + k*TM1 + 28 + tid] = (float)hashes[gk*T_ + t];
        } else if (tid == 2) {
            int l1 = lc[gk*T_ + i1], l2 = lc[gk*T_ + i2];
            out[O5 + k*TM1 + 30] = (float)(l1 + l2);
            int h1 = hashes[gk*T_ + i1], h2 = hashes[gk*T_ + i2];
            int mn = min(h1, h2), mx = max(h1, h2);
            unsigned int hh = ((unsigned int)mn * 1000003u + (unsigned int)mx) * 40503u + 2531011u;
            out[O6 + k*TM1 + 30] = (float)(int)hh;
        }
    } else {
        if (tid < RP1) {
            int r = tid;
            float v1, v2, vb1, vb2;
            if (r < R_) {
                v1 = (float)m1r[gk*R_ + r];
                v2 = (float)m2r[gk*R_ + r];
                vb1 = b1r[gk*R_ + r];
                vb2 = b2r[gk*R_ + r];
            } else {
                v1 = (float)i1; v2 = (float)i2;
                vb1 = br1[zs];  vb2 = br2[zs];
            }
            out[O0 + k*RP1 + r] = v1;
            out[O1 + k*RP1 + r] = v2;
            out[O2 + k*RP1 + r] = vb1;
            out[O3 + k*RP1 + r] = vb2;
        }
        const float4* s4 = (const float4*)(embr + (size_t)gk*R_*D_);
        float4* d4 = (float4*)(out + O4 + (size_t)k*RP1*D_);
        d4[tid] = s4[tid];
        d4[tid + 256] = s4[tid + 256];
        if (tid < 16) {
            const float4* j4 = (const float4*)(embJ + (size_t)zs*D_);
            d4[512 + tid] = j4[tid];
        }
    }
}

// ---------------- launch ----------------
extern "C" void kernel_launch(void* const* d_in, const int* in_sizes, int n_in,
                              void* d_out, int out_size) {
    const int*   indexes = (const int*)  d_in[0];
    const int*   m1r     = (const int*)  d_in[1];
    const int*   m2r     = (const int*)  d_in[2];
    const float* b1r     = (const float*)d_in[3];
    const float* b2r     = (const float*)d_in[4];
    const float* embr    = (const float*)d_in[5];
    const int*   lc      = (const int*)  d_in[6];
    const int*   hashes  = (const int*)  d_in[7];
    const float* embt    = (const float*)d_in[8];
    const float* lf      = (const float*)d_in[9];
    const float* log_pi  = (const float*)d_in[10];
    const int*   idx1a   = (const int*)  d_in[11];
    const int*   idx2a   = (const int*)  d_in[12];
    const float* br1     = (const float*)d_in[13];
    const float* br2     = (const float*)d_in[14];
    const float* embJ    = (const float*)d_in[15];
    const float* logvp   = (const float*)d_in[16];
    const float* gumbel  = (const float*)d_in[17];
    const float* Wq      = (const float*)d_in[18];
    const float* Wstat   = (const float*)d_in[19];
    const float* logdf   = (const float*)d_in[20];
    float* out = (float*)d_out;

    k1<<<4*K_ + Z_, 256>>>(indexes, lc, embt, lf, Wstat,
                           idx1a, idx2a, br1, br2, embJ, Wq);
    ksel<<<K_, 32>>>(indexes, lc, b1r, b2r, idx1a, idx2a, br1, br2,
                     log_pi, logvp, gumbel, logdf, out);
    k2<<<dim3(9, K_), 256>>>(lc, hashes, embt, lf, embJ, br1, br2,
                             m1r, m2r, b1r, b2r, embr, out);
}